// round 14
// baseline (speedup 1.0000x reference)
#include <cuda_runtime.h>
#include <cuda_bf16.h>
#include <cstdint>

// FlowBasedDensityPotential: energy = 0.5 * sum(|grad phi|^2), central diffs
// (one-sided at boundaries) on 2048x2048 f32. 'pos' input is dead.
//
// R14: fire-and-forget L2 prefetch + simple LDG compute.
// 10 structural variants (LDG/cp.async/TMA, occ 12-86%) all pinned at
// ~1.7TB/s: consumer-side in-flight bytes are capped and latency is
// DRAM-tier. cp.async.bulk.prefetch.L2 has NO consumer -> not latency
// bound; each CTA prefetches a contiguous ~14KB slice at t=0 (whole array
// in flight < 1us), DRAM->L2 fill runs at full rate, and the trailing LDG
// compute increasingly hits L2 (234cyc vs 577cyc -> 2.5x bandwidth at a
// fixed in-flight cap).

#define NX 2048
#define NY 2048
#define BLOCK 256
#define NUM_BLOCKS 1184                          // 8 * 148: exact occ-8 fit
#define NTHREAD (NUM_BLOCKS * BLOCK)             // 303104
#define TOTAL_TASKS (NX * (NY / 4))              // 1048576 float4 tasks
#define FINAL_SCALE 524288.0                     // 0.5 * (1/(2h))^2
#define TOTAL_BYTES (NX * NY * 4)                // 16777216
#define PF_BYTES 14336                           // per-CTA prefetch slice (14KB)

__device__ double       g_partials[NUM_BLOCKS];
__device__ unsigned int g_ticket = 0;

__global__ void __launch_bounds__(BLOCK, 8)
flow_energy_kernel(const float* __restrict__ phi, float* __restrict__ out)
{
    const int tid  = threadIdx.x;
    const int lane = tid & 31;
    const int t0   = blockIdx.x * BLOCK + tid;

    // ---- t=0: fire-and-forget bulk L2 prefetch of this CTA's slice ----
    if (tid == 0) {
        size_t off = (size_t)blockIdx.x * PF_BYTES;
        if (off < (size_t)TOTAL_BYTES) {
            unsigned int bytes = PF_BYTES;
            if (off + bytes > (size_t)TOTAL_BYTES)
                bytes = (unsigned int)((size_t)TOTAL_BYTES - off);
            asm volatile("cp.async.bulk.prefetch.L2.global [%0], %1;"
                         :: "l"((const char*)phi + off), "r"(bytes) : "memory");
        }
    }

    float acc = 0.0f;

    // Grid-stride compute (stride and total are multiples of 32).
    for (int task = t0; task < TOTAL_TASKS; task += NTHREAD) {
        const int i  = task >> 9;                // row
        const int j0 = (task & 511) * 4;         // first col of this float4

        const int iu = i > 0      ? i - 1 : 0;
        const int id = i < NX - 1 ? i + 1 : NX - 1;

        const float4 cur  = *reinterpret_cast<const float4*>(phi + (size_t)i  * NY + j0);
        const float4 up   = *reinterpret_cast<const float4*>(phi + (size_t)iu * NY + j0);
        const float4 down = *reinterpret_cast<const float4*>(phi + (size_t)id * NY + j0);

        float ex, ey, ez, ew;
        if (i == 0) {
            ex = (down.x - cur.x) * 2.0f;
            ey = (down.y - cur.y) * 2.0f;
            ez = (down.z - cur.z) * 2.0f;
            ew = (down.w - cur.w) * 2.0f;
        } else if (i == NX - 1) {
            ex = (cur.x - up.x) * 2.0f;
            ey = (cur.y - up.y) * 2.0f;
            ez = (cur.z - up.z) * 2.0f;
            ew = (cur.w - up.w) * 2.0f;
        } else {
            ex = down.x - up.x;
            ey = down.y - up.y;
            ez = down.z - up.z;
            ew = down.w - up.w;
        }

        // y halos from adjacent lanes; warp-edge lanes use predicated loads.
        float left  = __shfl_up_sync(0xffffffffu, cur.w, 1);
        float right = __shfl_down_sync(0xffffffffu, cur.x, 1);
        if (lane == 0 && j0 > 0)
            left = phi[(size_t)i * NY + j0 - 1];
        if (lane == 31 && j0 + 4 < NY)
            right = phi[(size_t)i * NY + j0 + 4];

        const float d0 = (j0 == 0)      ? (cur.y - cur.x) * 2.0f : (cur.y - left);
        const float d1 = cur.z - cur.x;
        const float d2 = cur.w - cur.y;
        const float d3 = (j0 + 4 == NY) ? (cur.w - cur.z) * 2.0f : (right - cur.z);

        acc += ex * ex + d0 * d0;
        acc += ey * ey + d1 * d1;
        acc += ez * ez + d2 * d2;
        acc += ew * ew + d3 * d3;
    }

    // ---- block reduction ----
    #pragma unroll
    for (int off = 16; off; off >>= 1)
        acc += __shfl_xor_sync(0xffffffffu, acc, off);

    __shared__ float  s_warp[BLOCK / 32];
    __shared__ bool   s_is_last;
    if ((tid & 31) == 0)
        s_warp[tid >> 5] = acc;
    __syncthreads();

    if (tid < 32) {
        float v = (tid < BLOCK / 32) ? s_warp[tid] : 0.0f;
        #pragma unroll
        for (int off = 4; off; off >>= 1)
            v += __shfl_xor_sync(0xffffffffu, v, off);
        if (tid == 0) {
            g_partials[blockIdx.x] = (double)v;
            __threadfence();
            unsigned int tk = atomicAdd(&g_ticket, 1u);
            s_is_last = (tk == (unsigned int)(gridDim.x - 1));
        }
    }
    __syncthreads();

    // ---- last block: sum 1184 double partials, scale, write, reset ----
    if (s_is_last) {
        double d = 0.0;
        for (int k = tid; k < NUM_BLOCKS; k += BLOCK)
            d += g_partials[k];
        #pragma unroll
        for (int off = 16; off; off >>= 1)
            d += __shfl_xor_sync(0xffffffffu, d, off);

        __shared__ double s_dwarp[BLOCK / 32];
        if ((tid & 31) == 0)
            s_dwarp[tid >> 5] = d;
        __syncthreads();
        if (tid < 32) {
            double v = (tid < BLOCK / 32) ? s_dwarp[tid] : 0.0;
            #pragma unroll
            for (int off = 4; off; off >>= 1)
                v += __shfl_xor_sync(0xffffffffu, v, off);
            if (tid == 0) {
                out[0] = (float)(v * FINAL_SCALE);
                g_ticket = 0;   // reset for next (graph-replayed) launch
            }
        }
    }
}

extern "C" void kernel_launch(void* const* d_in, const int* in_sizes, int n_in,
                              void* d_out, int out_size)
{
    // Select phi by element count (2048*2048); 'pos' (2,000,000 elems) unused.
    const float* phi = nullptr;
    for (int i = 0; i < n_in; ++i) {
        if (in_sizes[i] == NX * NY) { phi = (const float*)d_in[i]; break; }
    }
    if (!phi) phi = (const float*)d_in[n_in - 1];

    flow_energy_kernel<<<NUM_BLOCKS, BLOCK>>>(phi, (float*)d_out);
}

// round 15
// speedup vs baseline: 1.2012x; 1.2012x over previous
#include <cuda_runtime.h>
#include <cuda_bf16.h>
#include <cstdint>

// FlowBasedDensityPotential: energy = 0.5 * sum(|grad phi|^2), central diffs
// (one-sided at boundaries) on 2048x2048 f32. 'pos' input is dead.
//
// R15: lock-in of the best-measured variant (R10: 9.57us ncu, 10.72us wall).
// Eleven structural variants (LDG/cp.async/TMA/prefetch, occ 12-95%, MLP
// 2-14, L2-warm or cold) all land 9.6-11.5us ncu: the duration is a
// structure-invariant floor for this burst size on this part. R10's
// two-chunk staged TMA skeleton had the best ncu time, tied-best wall time,
// and the lowest instruction count; resubmitted with micro-trims only.

#define NX 2048
#define NY 2048
#define BLOCK 256
#define ROWS_PER_CTA 8
#define NUM_BLOCKS (NX / ROWS_PER_CTA)     // 256
#define PITCH NY
#define ROW_BYTES (NY * 4)                  // 8192
#define SROWS 10                            // 8 computed + 2 halo
#define TILE_BYTES (SROWS * ROW_BYTES)      // 81920
#define FINAL_SCALE 524288.0                // 0.5 * (1/(2h))^2 = 0.5*1024^2

__device__ double       g_partials[NUM_BLOCKS];
__device__ unsigned int g_ticket = 0;

extern __shared__ float s_tile[];           // SROWS * PITCH floats

__device__ __forceinline__ void mbar_init(unsigned int mbar, unsigned int cnt) {
    asm volatile("mbarrier.init.shared.b64 [%0], %1;" :: "r"(mbar), "r"(cnt) : "memory");
}
__device__ __forceinline__ void mbar_expect_tx(unsigned int mbar, unsigned int bytes) {
    asm volatile("mbarrier.arrive.expect_tx.shared.b64 _, [%0], %1;"
                 :: "r"(mbar), "r"(bytes) : "memory");
}
__device__ __forceinline__ void bulk_g2s(unsigned int sdst, const void* gsrc,
                                         unsigned int bytes, unsigned int mbar) {
    asm volatile("cp.async.bulk.shared::cta.global.mbarrier::complete_tx::bytes "
                 "[%0], [%1], %2, [%3];"
                 :: "r"(sdst), "l"(gsrc), "r"(bytes), "r"(mbar) : "memory");
}
__device__ __forceinline__ void mbar_wait(unsigned int mbar, unsigned int phase) {
    asm volatile("{\n\t"
                 ".reg .pred p;\n\t"
                 "WL%=:\n\t"
                 "mbarrier.try_wait.parity.shared.b64 p, [%0], %1;\n\t"
                 "@!p bra WL%=;\n\t"
                 "}" :: "r"(mbar), "r"(phase) : "memory");
}

__global__ void __launch_bounds__(BLOCK, 2)
flow_energy_kernel(const float* __restrict__ phi, float* __restrict__ out)
{
    __shared__ __align__(8) unsigned long long s_bar[2];
    __shared__ float  s_warp[BLOCK / 32];
    __shared__ double s_dwarp[BLOCK / 32];
    __shared__ bool   s_is_last;

    const int tid = threadIdx.x;
    const int b   = blockIdx.x;
    const int r0  = b * ROWS_PER_CTA;

    const unsigned int sbase = (unsigned int)__cvta_generic_to_shared(s_tile);
    const unsigned int bar0  = (unsigned int)__cvta_generic_to_shared(&s_bar[0]);
    const unsigned int bar1  = (unsigned int)__cvta_generic_to_shared(&s_bar[1]);

    if (tid == 0) {
        mbar_init(bar0, 1);
        mbar_init(bar1, 1);
    }
    __syncthreads();

    if (tid == 0) {
        // Chunk A: smem slots (b==0 ? 1 : 0) .. 5 == rows max(r0-1,0) .. r0+4
        const int gsA   = (b == 0) ? 0 : r0 - 1;
        const int slotA = (b == 0) ? 1 : 0;
        const unsigned int bytesA = (unsigned int)((6 - slotA) * ROW_BYTES);
        mbar_expect_tx(bar0, bytesA);
        bulk_g2s(sbase + (unsigned int)(slotA * ROW_BYTES),
                 phi + (size_t)gsA * NY, bytesA, bar0);

        // Chunk B: smem slots 6 .. (b==last ? 8 : 9) == rows r0+5 .. min(r0+8, NX-1)
        const int geB = (b == NUM_BLOCKS - 1) ? NX - 1 : r0 + 8;
        const unsigned int bytesB = (unsigned int)((geB - (r0 + 5) + 1) * ROW_BYTES);
        mbar_expect_tx(bar1, bytesB);
        bulk_g2s(sbase + (unsigned int)(6 * ROW_BYTES),
                 phi + (size_t)(r0 + 5) * NY, bytesB, bar1);
    }

    float acc = 0.0f;

    // Half h computes row slots (h*4+1 .. h*4+4) using window slots h*4 .. h*4+5.
    #pragma unroll
    for (int h = 0; h < 2; ++h) {
        mbar_wait(h == 0 ? bar0 : bar1, 0);

        #pragma unroll
        for (int pass = 0; pass < 2; ++pass) {
            const int cg = tid + pass * BLOCK;    // 0..511 column group
            const int c  = cg * 4;                // first col
            const int s0 = h * 4;                 // first window slot

            float4 w[6];
            #pragma unroll
            for (int k = 0; k < 6; ++k)
                w[k] = *reinterpret_cast<const float4*>(s_tile + (s0 + k) * PITCH + c);

            #pragma unroll
            for (int r = 0; r < 4; ++r) {
                const int slot = s0 + 1 + r;
                const int gi   = r0 + h * 4 + r;
                const float4 up   = w[r];
                const float4 cur  = w[r + 1];
                const float4 down = w[r + 2];

                float ex, ey, ez, ew;
                if (gi == 0) {
                    ex = (down.x - cur.x) * 2.0f;
                    ey = (down.y - cur.y) * 2.0f;
                    ez = (down.z - cur.z) * 2.0f;
                    ew = (down.w - cur.w) * 2.0f;
                } else if (gi == NX - 1) {
                    ex = (cur.x - up.x) * 2.0f;
                    ey = (cur.y - up.y) * 2.0f;
                    ez = (cur.z - up.z) * 2.0f;
                    ew = (cur.w - up.w) * 2.0f;
                } else {
                    ex = down.x - up.x;
                    ey = down.y - up.y;
                    ez = down.z - up.z;
                    ew = down.w - up.w;
                }

                // y halos from smem; clamped index stays in-bounds (clamped
                // values are select-discarded, never arithmetic inputs).
                const float left  = s_tile[slot * PITCH + c - 1 + (c == 0 ? 1 : 0)];
                const float right = s_tile[slot * PITCH + c + 4 - (c + 4 == NY ? 1 : 0)];

                const float d0 = (c == 0)      ? (cur.y - cur.x) * 2.0f : (cur.y - left);
                const float d1 = cur.z - cur.x;
                const float d2 = cur.w - cur.y;
                const float d3 = (c + 4 == NY) ? (cur.w - cur.z) * 2.0f : (right - cur.z);

                acc += ex * ex + d0 * d0;
                acc += ey * ey + d1 * d1;
                acc += ez * ez + d2 * d2;
                acc += ew * ew + d3 * d3;
            }
        }
    }

    // ---- block reduction ----
    #pragma unroll
    for (int off = 16; off; off >>= 1)
        acc += __shfl_xor_sync(0xffffffffu, acc, off);

    if ((tid & 31) == 0)
        s_warp[tid >> 5] = acc;
    __syncthreads();

    if (tid < 32) {
        float v = (tid < BLOCK / 32) ? s_warp[tid] : 0.0f;
        #pragma unroll
        for (int off = 4; off; off >>= 1)
            v += __shfl_xor_sync(0xffffffffu, v, off);
        if (tid == 0) {
            g_partials[blockIdx.x] = (double)v;
            __threadfence();
            unsigned int tk = atomicAdd(&g_ticket, 1u);
            s_is_last = (tk == (unsigned int)(gridDim.x - 1));
        }
    }
    __syncthreads();

    // ---- last block: 256 partials == one load per thread; sum, write, reset ----
    if (s_is_last) {
        double d = (tid < NUM_BLOCKS) ? g_partials[tid] : 0.0;
        #pragma unroll
        for (int off = 16; off; off >>= 1)
            d += __shfl_xor_sync(0xffffffffu, d, off);

        if ((tid & 31) == 0)
            s_dwarp[tid >> 5] = d;
        __syncthreads();
        if (tid < 32) {
            double v = (tid < BLOCK / 32) ? s_dwarp[tid] : 0.0;
            #pragma unroll
            for (int off = 4; off; off >>= 1)
                v += __shfl_xor_sync(0xffffffffu, v, off);
            if (tid == 0) {
                out[0] = (float)(v * FINAL_SCALE);
                g_ticket = 0;   // reset for next (graph-replayed) launch
            }
        }
    }
}

extern "C" void kernel_launch(void* const* d_in, const int* in_sizes, int n_in,
                              void* d_out, int out_size)
{
    // Select phi by element count (2048*2048); 'pos' (2,000,000 elems) unused.
    const float* phi = nullptr;
    for (int i = 0; i < n_in; ++i) {
        if (in_sizes[i] == NX * NY) { phi = (const float*)d_in[i]; break; }
    }
    if (!phi) phi = (const float*)d_in[n_in - 1];

    static bool attr_done = false;
    if (!attr_done) {
        cudaFuncSetAttribute(flow_energy_kernel,
                             cudaFuncAttributeMaxDynamicSharedMemorySize,
                             TILE_BYTES);
        attr_done = true;
    }

    flow_energy_kernel<<<NUM_BLOCKS, BLOCK, TILE_BYTES>>>(phi, (float*)d_out);
}